// round 14
// baseline (speedup 1.0000x reference)
#include <cuda_runtime.h>
#include <cuda_bf16.h>
#include <cstdint>

// Shapes (fixed): z (16,256,32,32) fp32; codebook (2048,256) fp32; out like z.
#define N_ROWS 16384
#define DDIM   256
#define KCODES 2048
#define HW     1024
#define CAND_CAP (1 << 22)   // 4M coarse candidates (expect ~870K)

// Margin: error enters twice (candidate overestimate + row-min underestimate),
// worst-case ~2.0e-3 -> 2.5e-3 is the SAFE minimum. Do not tighten.
#define MARGIN 2.5e-3f

// ---------------- device scratch (no mallocs allowed) ----------------
__device__ float              g_cnorm[KCODES];
__device__ uint32_t           g_minu[N_ROWS];
__device__ unsigned long long g_best[N_ROWS];
__device__ int                g_candCount;
__device__ unsigned long long g_cand[CAND_CAP];        // (coarse_bf16<<32)|(n<<11)|k
__device__ float              g_zt [N_ROWS * DDIM];    // token-major fp32 z
__device__ __nv_bfloat16      g_ztb[N_ROWS * DDIM];    // token-major bf16 z
__device__ __nv_bfloat16      g_cbb[KCODES * DDIM];    // bf16 codebook

// ---------------- small helpers ----------------
__device__ __forceinline__ uint32_t cvt_bf16x2(float a, float b) {  // lo=a, hi=b
    uint32_t r;
    asm("cvt.rn.bf16x2.f32 %0, %1, %2;" : "=r"(r) : "f"(b), "f"(a));
    return r;
}
__device__ __forceinline__ uint32_t fmap(float f) {
    uint32_t b = __float_as_uint(f);
    return (b & 0x80000000u) ? ~b : (b | 0x80000000u);
}
__device__ __forceinline__ float funmap(uint32_t u) {
    uint32_t b = (u & 0x80000000u) ? (u & 0x7fffffffu) : ~u;
    return __uint_as_float(b);
}
__device__ __forceinline__ void ldsm4(uint32_t& r0, uint32_t& r1, uint32_t& r2,
                                      uint32_t& r3, uint32_t addr) {
    asm volatile("ldmatrix.sync.aligned.m8n8.x4.shared.b16 {%0,%1,%2,%3}, [%4];"
                 : "=r"(r0), "=r"(r1), "=r"(r2), "=r"(r3) : "r"(addr));
}
__device__ __forceinline__ uint32_t smem_u32(const void* p) {
    uint32_t a;
    asm("{ .reg .u64 t; cvta.to.shared.u64 t, %1; cvt.u32.u64 %0, t; }" : "=r"(a) : "l"(p));
    return a;
}
__device__ __forceinline__ void mma16816(float* c, uint32_t a0, uint32_t a1,
                                         uint32_t a2, uint32_t a3,
                                         uint32_t b0, uint32_t b1) {
    asm volatile(
        "mma.sync.aligned.m16n8k16.row.col.f32.bf16.bf16.f32 "
        "{%0,%1,%2,%3}, {%4,%5,%6,%7}, {%8,%9}, {%0,%1,%2,%3};"
        : "+f"(c[0]), "+f"(c[1]), "+f"(c[2]), "+f"(c[3])
        : "r"(a0), "r"(a1), "r"(a2), "r"(a3), "r"(b0), "r"(b1));
}
__device__ __forceinline__ void cp16(uint32_t dst, const void* src) {
    asm volatile("cp.async.cg.shared.global [%0], [%1], 16;" :: "r"(dst), "l"(src));
}

// ---------------- (1) prep: transpose + init + cbcnorm (R12 version) --------
#define PREP_T_CTAS 4096
#define PREP_I_CTAS 64
#define PREP_GRID   (PREP_T_CTAS + PREP_I_CTAS + 8)

__global__ void __launch_bounds__(256) prep_kernel(const float* __restrict__ z,
                                                   const float* __restrict__ cb) {
    const int bx = blockIdx.x, t = threadIdx.x;
    if (bx < PREP_T_CTAS) {
        __shared__ float ts[32][33];
        int tx = t & 31, ty = t >> 5;
        int b  = bx >> 8;
        int rest = bx & 255;
        int pt = rest & 31, dt = rest >> 5;
        int p0 = pt * 32, d0 = dt * 32;
        #pragma unroll
        for (int i = 0; i < 4; i++) {
            int d = d0 + ty + i * 8;
            ts[ty + i * 8][tx] = z[((size_t)(b * DDIM + d)) * HW + p0 + tx];
        }
        __syncthreads();
        #pragma unroll
        for (int i = 0; i < 4; i++) {
            int n = b * HW + p0 + ty + i * 8;
            float v = ts[tx][ty + i * 8];
            g_zt [(size_t)n * DDIM + d0 + tx] = v;
            g_ztb[(size_t)n * DDIM + d0 + tx] = __float2bfloat16(v);
        }
    } else if (bx < PREP_T_CTAS + PREP_I_CTAS) {
        int n = (bx - PREP_T_CTAS) * 256 + t;
        g_minu[n] = 0xFFFFFFFFu;
        g_best[n] = 0xFFFFFFFFFFFFFFFFull;
        if (n == 0) g_candCount = 0;
    } else {
        int k = (bx - PREP_T_CTAS - PREP_I_CTAS) * 256 + t;
        const float4* row4 = reinterpret_cast<const float4*>(cb + (size_t)k * DDIM);
        uint32_t* out = reinterpret_cast<uint32_t*>(g_cbb + (size_t)k * DDIM);
        float s = 0.f;
        #pragma unroll 4
        for (int d4 = 0; d4 < DDIM / 4; d4++) {
            float4 v = row4[d4];
            s = __fmaf_rn(v.x, v.x, s);   // sequential chain (matched JAX 11x)
            s = __fmaf_rn(v.y, v.y, s);
            s = __fmaf_rn(v.z, v.z, s);
            s = __fmaf_rn(v.w, v.w, s);
            out[d4 * 2 + 0] = cvt_bf16x2(v.x, v.y);
            out[d4 * 2 + 1] = cvt_bf16x2(v.z, v.w);
        }
        g_cnorm[k] = s;
    }
}

// ---------------- (2) coarse GEMM: 128x256 tile, 512 thr, 3-stage cp.async --
// 16 warps as 4(m) x 4(n); warp tile 32x64 -> inner structure identical to
// the verified 256-thread kernel, only addressing/grid change.
#define PITCH 72
#define A_ROWS 128
#define B_ROWS 256
#define A_BYTES (A_ROWS * PITCH * 2)          // 18432
#define STAGE_BYTES ((A_ROWS + B_ROWS) * PITCH * 2)   // 55296
#define NSTAGE 3
#define MMA_SMEM (NSTAGE * STAGE_BYTES)       // 165888 dynamic
#define MMA_THREADS 512

__global__ void __launch_bounds__(MMA_THREADS, 1) mma_kernel() {
    extern __shared__ __align__(16) char dsm[];
    __shared__ int s_cnt, s_base;

    const int t = threadIdx.x, wid = t >> 5, lane = t & 31;
    const int row0 = blockIdx.x * 128, col0 = blockIdx.y * 256;
    const int wm = (wid & 3) * 32;            // 4 m-positions
    const int wn = (wid >> 2) * 64;           // 4 n-positions (256 total)
    const int r  = lane >> 2, tt = lane & 3;
    const int grp = lane >> 3, l7 = lane & 7;

    const int a_row = (grp & 1) * 8 + l7, a_k = (grp & 2) * 4;
    const int b_row = (grp & 2) * 4 + l7, b_k = (grp & 1) * 8;
    const uint32_t sbase = smem_u32(dsm);
    uint32_t aOff[2], bOff[4];                // stage-relative
    #pragma unroll
    for (int mt = 0; mt < 2; mt++)
        aOff[mt] = ((wm + mt * 16 + a_row) * PITCH + a_k) * 2;
    #pragma unroll
    for (int p = 0; p < 4; p++)
        bOff[p] = A_BYTES + ((wn + p * 16 + b_row) * PITCH + b_k) * 2;

    float acc[2][8][4];
    #pragma unroll
    for (int mt = 0; mt < 2; mt++)
        #pragma unroll
        for (int nt = 0; nt < 8; nt++)
            #pragma unroll
            for (int q = 0; q < 4; q++) acc[mt][nt][q] = 0.f;

    // stage = 384 rows (128 A + 256 B) x 8 float4-slots = 3072 slots, 6 iters
    auto prefetch = [&](int ch) {
        const int s = ch % NSTAGE, cd0 = ch * 64;
        const uint32_t buf = sbase + s * STAGE_BYTES;
        #pragma unroll
        for (int it = 0; it < 6; it++) {
            int idx = it * MMA_THREADS + t;
            int rr = idx >> 3, k8 = (idx & 7) * 8;
            uint32_t off = (rr * PITCH + k8) * 2;
            const void* src = (rr < A_ROWS)
                ? (const void*)&g_ztb[(size_t)(row0 + rr) * DDIM + cd0 + k8]
                : (const void*)&g_cbb[(size_t)(col0 + rr - A_ROWS) * DDIM + cd0 + k8];
            cp16(buf + off, src);
        }
        asm volatile("cp.async.commit_group;" ::: "memory");
    };

    prefetch(0);
    prefetch(1);
    for (int ch = 0; ch < 4; ch++) {
        if (ch < 3) asm volatile("cp.async.wait_group 1;" ::: "memory");
        else        asm volatile("cp.async.wait_group 0;" ::: "memory");
        __syncthreads();
        if (ch < 2) prefetch(ch + 2);

        const uint32_t sb = sbase + (ch % NSTAGE) * STAGE_BYTES;
        #pragma unroll
        for (int ks = 0; ks < 4; ks++) {
            const uint32_t koff = ks * 32;
            uint32_t A0[4], A1[4];
            ldsm4(A0[0], A0[1], A0[2], A0[3], sb + aOff[0] + koff);
            ldsm4(A1[0], A1[1], A1[2], A1[3], sb + aOff[1] + koff);
            #pragma unroll
            for (int p = 0; p < 4; p++) {
                uint32_t B[4];
                ldsm4(B[0], B[1], B[2], B[3], sb + bOff[p] + koff);
                mma16816(acc[0][2 * p],     A0[0], A0[1], A0[2], A0[3], B[0], B[1]);
                mma16816(acc[0][2 * p + 1], A0[0], A0[1], A0[2], A0[3], B[2], B[3]);
                mma16816(acc[1][2 * p],     A1[0], A1[1], A1[2], A1[3], B[0], B[1]);
                mma16816(acc[1][2 * p + 1], A1[0], A1[1], A1[2], A1[3], B[2], B[3]);
            }
        }
    }
    __syncthreads();

    // --- epilogue: coarse = cnorm - 2*dot; warp row mins; emission ---
    float rmin[2][2];
    #pragma unroll
    for (int mt = 0; mt < 2; mt++) { rmin[mt][0] = 3.4e38f; rmin[mt][1] = 3.4e38f; }
    #pragma unroll
    for (int mt = 0; mt < 2; mt++)
        #pragma unroll
        for (int nt = 0; nt < 8; nt++) {
            const int cbase = col0 + wn + nt * 8;
            float2 cn = *reinterpret_cast<const float2*>(&g_cnorm[cbase + tt * 2]);
            float d0 = __fmaf_rn(-2.f, acc[mt][nt][0], cn.x);
            float d1 = __fmaf_rn(-2.f, acc[mt][nt][1], cn.y);
            float d2 = __fmaf_rn(-2.f, acc[mt][nt][2], cn.x);
            float d3 = __fmaf_rn(-2.f, acc[mt][nt][3], cn.y);
            acc[mt][nt][0] = d0; acc[mt][nt][1] = d1;
            acc[mt][nt][2] = d2; acc[mt][nt][3] = d3;
            rmin[mt][0] = fminf(rmin[mt][0], fminf(d0, d1));
            rmin[mt][1] = fminf(rmin[mt][1], fminf(d2, d3));
        }
    #pragma unroll
    for (int mt = 0; mt < 2; mt++)
        #pragma unroll
        for (int h = 0; h < 2; h++)
            #pragma unroll
            for (int off = 1; off < 4; off <<= 1)
                rmin[mt][h] = fminf(rmin[mt][h],
                                    __shfl_xor_sync(0xffffffffu, rmin[mt][h], off));

    float gmv[2][2];
    if (tt == 0) {
        #pragma unroll
        for (int mt = 0; mt < 2; mt++) {
            const int grow = row0 + wm + mt * 16 + r;
            uint32_t o0 = atomicMin(&g_minu[grow],     fmap(rmin[mt][0]));
            uint32_t o1 = atomicMin(&g_minu[grow + 8], fmap(rmin[mt][1]));
            gmv[mt][0] = funmap(o0);   // NaN if untouched; fminf ignores NaN
            gmv[mt][1] = funmap(o1);
        }
    }
    const int src = lane & ~3;
    float th[2][2];
    #pragma unroll
    for (int mt = 0; mt < 2; mt++)
        #pragma unroll
        for (int h = 0; h < 2; h++) {
            float g = __shfl_sync(0xffffffffu, gmv[mt][h], src);
            th[mt][h] = fminf(rmin[mt][h], g) + (MARGIN + 1e-4f);
        }

    if (t == 0) s_cnt = 0;
    int cnt = 0;
    #pragma unroll
    for (int mt = 0; mt < 2; mt++)
        #pragma unroll
        for (int nt = 0; nt < 8; nt++)
            #pragma unroll
            for (int q = 0; q < 4; q++)
                cnt += (acc[mt][nt][q] <= th[mt][q >> 1]) ? 1 : 0;

    int pref = cnt;
    #pragma unroll
    for (int off = 1; off < 32; off <<= 1) {
        int v = __shfl_up_sync(0xffffffffu, pref, off);
        if (lane >= off) pref += v;
    }
    int excl = pref - cnt;
    __syncthreads();
    int wbase = 0;
    if (lane == 31) wbase = atomicAdd(&s_cnt, pref);
    wbase = __shfl_sync(0xffffffffu, wbase, 31);
    __syncthreads();
    if (t == 0) s_base = s_cnt ? atomicAdd(&g_candCount, s_cnt) : 0;
    __syncthreads();
    int pos = s_base + wbase + excl;

    #pragma unroll
    for (int mt = 0; mt < 2; mt++)
        #pragma unroll
        for (int nt = 0; nt < 8; nt++)
            #pragma unroll
            for (int q = 0; q < 4; q++) {
                float d = acc[mt][nt][q];
                if (d <= th[mt][q >> 1]) {
                    if (pos < CAND_CAP) {
                        int grow = row0 + wm + mt * 16 + r + ((q >> 1) ? 8 : 0);
                        int k    = col0 + wn + nt * 8 + tt * 2 + (q & 1);
                        uint32_t dbits =
                            (uint32_t)__bfloat16_as_ushort(__float2bfloat16(d));
                        g_cand[pos] = ((unsigned long long)dbits << 32)
                                    | ((uint32_t)grow << 11) | (uint32_t)k;
                    }
                    pos++;
                }
            }
}

// ---------------- (3) rescore: inline filter + exact chain ----------------
#define RS_GRID 1024

__global__ void __launch_bounds__(256) rescore_kernel(const float* __restrict__ cb) {
    int total = g_candCount; if (total > CAND_CAP) total = CAND_CAP;
    for (int i = blockIdx.x * 256 + threadIdx.x; i < total; i += RS_GRID * 256) {
        unsigned long long e = g_cand[i];
        uint32_t nk = (uint32_t)e & 0x1FFFFFFu;
        int n = nk >> 11, k = nk & 2047;
        float coarse =
            __bfloat162float(__ushort_as_bfloat16((unsigned short)(e >> 32)));
        if (coarse <= funmap(g_minu[n]) + MARGIN) {
            const float4* za4 = reinterpret_cast<const float4*>(g_zt + (size_t)n * DDIM);
            const float4* ca4 = reinterpret_cast<const float4*>(cb + (size_t)k * DDIM);
            float acc = 0.f, zn = 0.f;
            #pragma unroll 8
            for (int d4 = 0; d4 < DDIM / 4; d4++) {
                float4 a = za4[d4], c = ca4[d4];
                zn  = __fmaf_rn(a.x, a.x, zn);    // znorm chain (verified 11x)
                zn  = __fmaf_rn(a.y, a.y, zn);
                zn  = __fmaf_rn(a.z, a.z, zn);
                zn  = __fmaf_rn(a.w, a.w, zn);
                acc = __fmaf_rn(a.x, c.x, acc);   // dot chain (verified 11x)
                acc = __fmaf_rn(a.y, c.y, acc);
                acc = __fmaf_rn(a.z, c.z, acc);
                acc = __fmaf_rn(a.w, c.w, acc);
            }
            float dist = __fadd_rn(__fadd_rn(zn, g_cnorm[k]), -2.0f * acc);
            unsigned long long pk =
                ((unsigned long long)__float_as_uint(dist) << 32) | (unsigned)k;
            atomicMin(&g_best[n], pk);
        }
    }
}

// ---------------- (4) gather + STE with smem-staged codebook rows ----------
#define GT 32   // tokens per CTA

__global__ void __launch_bounds__(256) gather_kernel(const float* __restrict__ z,
                                                     const float* __restrict__ cb,
                                                     float* __restrict__ out) {
    __shared__ float cbrow[GT][DDIM + 1];
    __shared__ int ks[GT];
    const int t = threadIdx.x;
    const int n0 = blockIdx.x * GT;
    const int b = n0 >> 10, p0 = n0 & 1023;

    if (t < GT) ks[t] = (int)(g_best[n0 + t] & 0xffffffffu);
    __syncthreads();

    #pragma unroll
    for (int it = 0; it < (GT * DDIM / 4) / 256; it++) {
        int slot = it * 256 + t;
        int tok = slot >> 6, c4 = slot & 63;
        float4 v = reinterpret_cast<const float4*>(cb + (size_t)ks[tok] * DDIM)[c4];
        cbrow[tok][c4 * 4 + 0] = v.x;
        cbrow[tok][c4 * 4 + 1] = v.y;
        cbrow[tok][c4 * 4 + 2] = v.z;
        cbrow[tok][c4 * 4 + 3] = v.w;
    }
    __syncthreads();

    const size_t zbase = (size_t)b * DDIM * HW + p0;
    #pragma unroll
    for (int it = 0; it < 8; it++) {
        int slot = it * 256 + t;
        int d = slot >> 3, p4 = slot & 7;
        size_t off = zbase + (size_t)d * HW + p4 * 4;
        float4 zv = *reinterpret_cast<const float4*>(z + off);
        float q0 = cbrow[p4 * 4 + 0][d];
        float q1 = cbrow[p4 * 4 + 1][d];
        float q2 = cbrow[p4 * 4 + 2][d];
        float q3 = cbrow[p4 * 4 + 3][d];
        float4 r;
        r.x = __fadd_rn(zv.x, __fadd_rn(q0, -zv.x));   // STE chain (matched 11x)
        r.y = __fadd_rn(zv.y, __fadd_rn(q1, -zv.y));
        r.z = __fadd_rn(zv.z, __fadd_rn(q2, -zv.z));
        r.w = __fadd_rn(zv.w, __fadd_rn(q3, -zv.w));
        *reinterpret_cast<float4*>(out + off) = r;
    }
}

// ---------------------------------------------------------------------------
extern "C" void kernel_launch(void* const* d_in, const int* in_sizes, int n_in,
                              void* d_out, int out_size) {
    const float* z  = (const float*)d_in[0];
    const float* cb = (const float*)d_in[1];
    float* out = (float*)d_out;

    cudaFuncSetAttribute(mma_kernel,
                         cudaFuncAttributeMaxDynamicSharedMemorySize, MMA_SMEM);

    prep_kernel<<<PREP_GRID, 256>>>(z, cb);                            // 1
    mma_kernel<<<dim3(N_ROWS / 128, KCODES / 256), MMA_THREADS, MMA_SMEM>>>(); // 2
    rescore_kernel<<<RS_GRID, 256>>>(cb);                              // 3
    gather_kernel<<<N_ROWS / GT, 256>>>(z, cb, out);                   // 4
}

// round 15
// speedup vs baseline: 1.1132x; 1.1132x over previous
#include <cuda_runtime.h>
#include <cuda_bf16.h>
#include <cstdint>

// Shapes (fixed): z (16,256,32,32) fp32; codebook (2048,256) fp32; out like z.
#define N_ROWS 16384
#define DDIM   256
#define KCODES 2048
#define HW     1024
#define NBUCK  256       // 64-token buckets
#define BCAP   8192      // per-bucket candidate cap (expect ~3.4K avg)

// Margin: error enters twice (candidate overestimate + row-min underestimate),
// worst-case ~2.0e-3 -> 2.5e-3 is the SAFE minimum. Do not tighten.
#define MARGIN 2.5e-3f

// ---------------- device scratch (no mallocs allowed) ----------------
__device__ float              g_cnorm[KCODES];
__device__ uint32_t           g_minu[N_ROWS];
__device__ unsigned long long g_best[N_ROWS];
__device__ int                g_bcnt[NBUCK];
__device__ unsigned long long g_bcand[(size_t)NBUCK * BCAP]; // (coarse_bf16<<32)|(n<<11)|k
__device__ __nv_bfloat16      g_ztb[N_ROWS * DDIM];    // token-major bf16 z
__device__ __nv_bfloat16      g_cbb[KCODES * DDIM];    // bf16 codebook

// ---------------- small helpers ----------------
__device__ __forceinline__ uint32_t cvt_bf16x2(float a, float b) {  // lo=a, hi=b
    uint32_t r;
    asm("cvt.rn.bf16x2.f32 %0, %1, %2;" : "=r"(r) : "f"(b), "f"(a));
    return r;
}
__device__ __forceinline__ uint32_t fmap(float f) {
    uint32_t b = __float_as_uint(f);
    return (b & 0x80000000u) ? ~b : (b | 0x80000000u);
}
__device__ __forceinline__ float funmap(uint32_t u) {
    uint32_t b = (u & 0x80000000u) ? (u & 0x7fffffffu) : ~u;
    return __uint_as_float(b);
}
__device__ __forceinline__ void ldsm4(uint32_t& r0, uint32_t& r1, uint32_t& r2,
                                      uint32_t& r3, uint32_t addr) {
    asm volatile("ldmatrix.sync.aligned.m8n8.x4.shared.b16 {%0,%1,%2,%3}, [%4];"
                 : "=r"(r0), "=r"(r1), "=r"(r2), "=r"(r3) : "r"(addr));
}
__device__ __forceinline__ uint32_t smem_u32(const void* p) {
    uint32_t a;
    asm("{ .reg .u64 t; cvta.to.shared.u64 t, %1; cvt.u32.u64 %0, t; }" : "=r"(a) : "l"(p));
    return a;
}
__device__ __forceinline__ void mma16816(float* c, uint32_t a0, uint32_t a1,
                                         uint32_t a2, uint32_t a3,
                                         uint32_t b0, uint32_t b1) {
    asm volatile(
        "mma.sync.aligned.m16n8k16.row.col.f32.bf16.bf16.f32 "
        "{%0,%1,%2,%3}, {%4,%5,%6,%7}, {%8,%9}, {%0,%1,%2,%3};"
        : "+f"(c[0]), "+f"(c[1]), "+f"(c[2]), "+f"(c[3])
        : "r"(a0), "r"(a1), "r"(a2), "r"(a3), "r"(b0), "r"(b1));
}
__device__ __forceinline__ void cp16(uint32_t dst, const void* src) {
    asm volatile("cp.async.cg.shared.global [%0], [%1], 16;" :: "r"(dst), "l"(src));
}

// ---------------- (1) prep: transpose(bf16 only) + init + cbcnorm -----------
#define PREP_T_CTAS 4096
#define PREP_I_CTAS 64
#define PREP_GRID   (PREP_T_CTAS + PREP_I_CTAS + 8)

__global__ void __launch_bounds__(256) prep_kernel(const float* __restrict__ z,
                                                   const float* __restrict__ cb) {
    const int bx = blockIdx.x, t = threadIdx.x;
    if (bx < PREP_T_CTAS) {
        __shared__ float ts[32][33];
        int tx = t & 31, ty = t >> 5;
        int b  = bx >> 8;
        int rest = bx & 255;
        int pt = rest & 31, dt = rest >> 5;
        int p0 = pt * 32, d0 = dt * 32;
        #pragma unroll
        for (int i = 0; i < 4; i++) {
            int d = d0 + ty + i * 8;
            ts[ty + i * 8][tx] = z[((size_t)(b * DDIM + d)) * HW + p0 + tx];
        }
        __syncthreads();
        #pragma unroll
        for (int i = 0; i < 4; i++) {
            int n = b * HW + p0 + ty + i * 8;
            g_ztb[(size_t)n * DDIM + d0 + tx] = __float2bfloat16(ts[tx][ty + i * 8]);
        }
    } else if (bx < PREP_T_CTAS + PREP_I_CTAS) {
        int n = (bx - PREP_T_CTAS) * 256 + t;
        g_minu[n] = 0xFFFFFFFFu;
        g_best[n] = 0xFFFFFFFFFFFFFFFFull;
        if (n < NBUCK) g_bcnt[n] = 0;
    } else {
        int k = (bx - PREP_T_CTAS - PREP_I_CTAS) * 256 + t;
        const float4* row4 = reinterpret_cast<const float4*>(cb + (size_t)k * DDIM);
        uint32_t* out = reinterpret_cast<uint32_t*>(g_cbb + (size_t)k * DDIM);
        float s = 0.f;
        #pragma unroll 4
        for (int d4 = 0; d4 < DDIM / 4; d4++) {
            float4 v = row4[d4];
            s = __fmaf_rn(v.x, v.x, s);   // sequential chain (matched JAX 12x)
            s = __fmaf_rn(v.y, v.y, s);
            s = __fmaf_rn(v.z, v.z, s);
            s = __fmaf_rn(v.w, v.w, s);
            out[d4 * 2 + 0] = cvt_bf16x2(v.x, v.y);
            out[d4 * 2 + 1] = cvt_bf16x2(v.z, v.w);
        }
        g_cnorm[k] = s;
    }
}

// ---------------- (2) coarse GEMM: R12 mainloop + bucketed emission ---------
#define PITCH 72
#define A_BYTES (128 * PITCH * 2)        // 18432
#define STAGE_BYTES (2 * A_BYTES)        // 36864 (A + B per stage)
#define NSTAGE 3
#define MMA_SMEM (NSTAGE * STAGE_BYTES)  // 110592 dynamic

__global__ void __launch_bounds__(256, 2) mma_kernel() {
    extern __shared__ __align__(16) char dsm[];

    const int t = threadIdx.x, wid = t >> 5, lane = t & 31;
    const int row0 = blockIdx.x * 128, col0 = blockIdx.y * 128;
    const int wm = (wid & 3) * 32;
    const int wn = (wid >> 2) * 64;
    const int r  = lane >> 2, tt = lane & 3;
    const int grp = lane >> 3, l7 = lane & 7;

    const int a_row = (grp & 1) * 8 + l7, a_k = (grp & 2) * 4;
    const int b_row = (grp & 2) * 4 + l7, b_k = (grp & 1) * 8;
    const uint32_t sbase = smem_u32(dsm);
    uint32_t aOff[2], bOff[4];                   // stage-relative
    #pragma unroll
    for (int mt = 0; mt < 2; mt++)
        aOff[mt] = ((wm + mt * 16 + a_row) * PITCH + a_k) * 2;
    #pragma unroll
    for (int p = 0; p < 4; p++)
        bOff[p] = A_BYTES + ((wn + p * 16 + b_row) * PITCH + b_k) * 2;

    float acc[2][8][4];
    #pragma unroll
    for (int mt = 0; mt < 2; mt++)
        #pragma unroll
        for (int nt = 0; nt < 8; nt++)
            #pragma unroll
            for (int q = 0; q < 4; q++) acc[mt][nt][q] = 0.f;

    auto prefetch = [&](int ch) {
        const int s = ch % NSTAGE, cd0 = ch * 64;
        const uint32_t abuf = sbase + s * STAGE_BYTES;
        const uint32_t bbuf = abuf + A_BYTES;
        #pragma unroll
        for (int it = 0; it < 4; it++) {
            int idx = it * 256 + t;
            int rr = idx >> 3, k8 = (idx & 7) * 8;
            uint32_t off = (rr * PITCH + k8) * 2;
            cp16(abuf + off, &g_ztb[(size_t)(row0 + rr) * DDIM + cd0 + k8]);
            cp16(bbuf + off, &g_cbb[(size_t)(col0 + rr) * DDIM + cd0 + k8]);
        }
        asm volatile("cp.async.commit_group;" ::: "memory");
    };

    prefetch(0);
    prefetch(1);
    for (int ch = 0; ch < 4; ch++) {
        if (ch < 3) asm volatile("cp.async.wait_group 1;" ::: "memory");
        else        asm volatile("cp.async.wait_group 0;" ::: "memory");
        __syncthreads();
        if (ch < 2) prefetch(ch + 2);

        const uint32_t sb = sbase + (ch % NSTAGE) * STAGE_BYTES;
        #pragma unroll
        for (int ks = 0; ks < 4; ks++) {
            const uint32_t koff = ks * 32;
            uint32_t A0[4], A1[4];
            ldsm4(A0[0], A0[1], A0[2], A0[3], sb + aOff[0] + koff);
            ldsm4(A1[0], A1[1], A1[2], A1[3], sb + aOff[1] + koff);
            #pragma unroll
            for (int p = 0; p < 4; p++) {
                uint32_t B[4];
                ldsm4(B[0], B[1], B[2], B[3], sb + bOff[p] + koff);
                mma16816(acc[0][2 * p],     A0[0], A0[1], A0[2], A0[3], B[0], B[1]);
                mma16816(acc[0][2 * p + 1], A0[0], A0[1], A0[2], A0[3], B[2], B[3]);
                mma16816(acc[1][2 * p],     A1[0], A1[1], A1[2], A1[3], B[0], B[1]);
                mma16816(acc[1][2 * p + 1], A1[0], A1[1], A1[2], A1[3], B[2], B[3]);
            }
        }
    }

    // --- epilogue: coarse = cnorm - 2*dot; warp row mins; bucketed emission --
    float rmin[2][2];
    #pragma unroll
    for (int mt = 0; mt < 2; mt++) { rmin[mt][0] = 3.4e38f; rmin[mt][1] = 3.4e38f; }
    #pragma unroll
    for (int mt = 0; mt < 2; mt++)
        #pragma unroll
        for (int nt = 0; nt < 8; nt++) {
            const int cbase = col0 + wn + nt * 8;
            float2 cn = *reinterpret_cast<const float2*>(&g_cnorm[cbase + tt * 2]);
            float d0 = __fmaf_rn(-2.f, acc[mt][nt][0], cn.x);
            float d1 = __fmaf_rn(-2.f, acc[mt][nt][1], cn.y);
            float d2 = __fmaf_rn(-2.f, acc[mt][nt][2], cn.x);
            float d3 = __fmaf_rn(-2.f, acc[mt][nt][3], cn.y);
            acc[mt][nt][0] = d0; acc[mt][nt][1] = d1;
            acc[mt][nt][2] = d2; acc[mt][nt][3] = d3;
            rmin[mt][0] = fminf(rmin[mt][0], fminf(d0, d1));
            rmin[mt][1] = fminf(rmin[mt][1], fminf(d2, d3));
        }
    #pragma unroll
    for (int mt = 0; mt < 2; mt++)
        #pragma unroll
        for (int h = 0; h < 2; h++)
            #pragma unroll
            for (int off = 1; off < 4; off <<= 1)
                rmin[mt][h] = fminf(rmin[mt][h],
                                    __shfl_xor_sync(0xffffffffu, rmin[mt][h], off));

    float gmv[2][2];
    if (tt == 0) {
        #pragma unroll
        for (int mt = 0; mt < 2; mt++) {
            const int grow = row0 + wm + mt * 16 + r;
            uint32_t o0 = atomicMin(&g_minu[grow],     fmap(rmin[mt][0]));
            uint32_t o1 = atomicMin(&g_minu[grow + 8], fmap(rmin[mt][1]));
            gmv[mt][0] = funmap(o0);   // NaN if untouched; fminf ignores NaN
            gmv[mt][1] = funmap(o1);
        }
    }
    const int src = lane & ~3;
    float th[2][2];
    #pragma unroll
    for (int mt = 0; mt < 2; mt++)
        #pragma unroll
        for (int h = 0; h < 2; h++) {
            float g = __shfl_sync(0xffffffffu, gmv[mt][h], src);
            th[mt][h] = fminf(rmin[mt][h], g) + (MARGIN + 1e-4f);
        }

    // all of this warp's rows (wm..wm+31) lie in ONE 64-token bucket
    const int bkt = (row0 >> 6) + (wm >= 64 ? 1 : 0);

    int cnt = 0;
    #pragma unroll
    for (int mt = 0; mt < 2; mt++)
        #pragma unroll
        for (int nt = 0; nt < 8; nt++)
            #pragma unroll
            for (int q = 0; q < 4; q++)
                cnt += (acc[mt][nt][q] <= th[mt][q >> 1]) ? 1 : 0;

    int pref = cnt;
    #pragma unroll
    for (int off = 1; off < 32; off <<= 1) {
        int v = __shfl_up_sync(0xffffffffu, pref, off);
        if (lane >= off) pref += v;
    }
    int excl = pref - cnt;
    int wbase = 0;
    if (lane == 31 && pref > 0) wbase = atomicAdd(&g_bcnt[bkt], pref);
    wbase = __shfl_sync(0xffffffffu, wbase, 31);
    int pos = wbase + excl;

    unsigned long long* bdst = g_bcand + (size_t)bkt * BCAP;
    #pragma unroll
    for (int mt = 0; mt < 2; mt++)
        #pragma unroll
        for (int nt = 0; nt < 8; nt++)
            #pragma unroll
            for (int q = 0; q < 4; q++) {
                float d = acc[mt][nt][q];
                if (d <= th[mt][q >> 1]) {
                    if (pos < BCAP) {
                        int grow = row0 + wm + mt * 16 + r + ((q >> 1) ? 8 : 0);
                        int k    = col0 + wn + nt * 8 + tt * 2 + (q & 1);
                        uint32_t dbits =
                            (uint32_t)__bfloat16_as_ushort(__float2bfloat16(d));
                        bdst[pos] = ((unsigned long long)dbits << 32)
                                  | ((uint32_t)grow << 11) | (uint32_t)k;
                    }
                    pos++;
                }
            }
}

// ---------------- (3) rescore: bucket CTA stages its z tile from z ----------
// One CTA per 64-token bucket. Loads z rows (coalesced fp32), transposes to
// smem (pitch 261 -> conflict-light), rescores with the identical exact
// chains (same fp32 values, same ascending-d order -> bitwise identical).
#define RPITCH 261
#define RS_SMEM (64 * RPITCH * 4)   // 66816 bytes

__global__ void __launch_bounds__(256) rescore_kernel(const float* __restrict__ z,
                                                      const float* __restrict__ cb) {
    extern __shared__ float zt[];   // [64 tokens][RPITCH]
    const int bkt = blockIdx.x, t = threadIdx.x;
    const int n0 = bkt * 64;
    const int b = n0 >> 10, p0 = n0 & 1023;   // 64 | 1024 -> single b

    // stage: 256 d-rows x 16 float4 p-slots
    #pragma unroll
    for (int it = 0; it < 16; it++) {
        int idx = it * 256 + t;
        int d = idx >> 4, s = idx & 15;
        float4 v = *reinterpret_cast<const float4*>(
            &z[((size_t)(b * DDIM + d)) * HW + p0 + s * 4]);
        zt[(s * 4 + 0) * RPITCH + d] = v.x;
        zt[(s * 4 + 1) * RPITCH + d] = v.y;
        zt[(s * 4 + 2) * RPITCH + d] = v.z;
        zt[(s * 4 + 3) * RPITCH + d] = v.w;
    }
    __syncthreads();

    int cnt = g_bcnt[bkt]; if (cnt > BCAP) cnt = BCAP;
    const unsigned long long* bc = g_bcand + (size_t)bkt * BCAP;
    for (int i = t; i < cnt; i += 256) {
        unsigned long long e = bc[i];
        uint32_t nk = (uint32_t)e & 0x1FFFFFFu;
        int n = nk >> 11, k = nk & 2047;
        float coarse =
            __bfloat162float(__ushort_as_bfloat16((unsigned short)(e >> 32)));
        if (coarse <= funmap(g_minu[n]) + MARGIN) {
            const float* zr = zt + (n & 63) * RPITCH;
            const float4* ca4 = reinterpret_cast<const float4*>(cb + (size_t)k * DDIM);
            float acc = 0.f, zn = 0.f;
            #pragma unroll 8
            for (int d4 = 0; d4 < DDIM / 4; d4++) {
                float a0 = zr[d4 * 4 + 0], a1 = zr[d4 * 4 + 1];
                float a2 = zr[d4 * 4 + 2], a3 = zr[d4 * 4 + 3];
                float4 c = ca4[d4];
                zn  = __fmaf_rn(a0, a0, zn);     // znorm chain (verified 12x)
                zn  = __fmaf_rn(a1, a1, zn);
                zn  = __fmaf_rn(a2, a2, zn);
                zn  = __fmaf_rn(a3, a3, zn);
                acc = __fmaf_rn(a0, c.x, acc);   // dot chain (verified 12x)
                acc = __fmaf_rn(a1, c.y, acc);
                acc = __fmaf_rn(a2, c.z, acc);
                acc = __fmaf_rn(a3, c.w, acc);
            }
            float dist = __fadd_rn(__fadd_rn(zn, g_cnorm[k]), -2.0f * acc);
            unsigned long long pk =
                ((unsigned long long)__float_as_uint(dist) << 32) | (unsigned)k;
            atomicMin(&g_best[n], pk);
        }
    }
}

// ---------------- (4) gather + STE with smem-staged codebook rows ----------
#define GT 32   // tokens per CTA

__global__ void __launch_bounds__(256) gather_kernel(const float* __restrict__ z,
                                                     const float* __restrict__ cb,
                                                     float* __restrict__ out) {
    __shared__ float cbrow[GT][DDIM + 1];
    __shared__ int ks[GT];
    const int t = threadIdx.x;
    const int n0 = blockIdx.x * GT;
    const int b = n0 >> 10, p0 = n0 & 1023;

    if (t < GT) ks[t] = (int)(g_best[n0 + t] & 0xffffffffu);
    __syncthreads();

    #pragma unroll
    for (int it = 0; it < (GT * DDIM / 4) / 256; it++) {
        int slot = it * 256 + t;
        int tok = slot >> 6, c4 = slot & 63;
        float4 v = reinterpret_cast<const float4*>(cb + (size_t)ks[tok] * DDIM)[c4];
        cbrow[tok][c4 * 4 + 0] = v.x;
        cbrow[tok][c4 * 4 + 1] = v.y;
        cbrow[tok][c4 * 4 + 2] = v.z;
        cbrow[tok][c4 * 4 + 3] = v.w;
    }
    __syncthreads();

    const size_t zbase = (size_t)b * DDIM * HW + p0;
    #pragma unroll
    for (int it = 0; it < 8; it++) {
        int slot = it * 256 + t;
        int d = slot >> 3, p4 = slot & 7;
        size_t off = zbase + (size_t)d * HW + p4 * 4;
        float4 zv = *reinterpret_cast<const float4*>(z + off);
        float q0 = cbrow[p4 * 4 + 0][d];
        float q1 = cbrow[p4 * 4 + 1][d];
        float q2 = cbrow[p4 * 4 + 2][d];
        float q3 = cbrow[p4 * 4 + 3][d];
        float4 r;
        r.x = __fadd_rn(zv.x, __fadd_rn(q0, -zv.x));   // STE chain (matched 12x)
        r.y = __fadd_rn(zv.y, __fadd_rn(q1, -zv.y));
        r.z = __fadd_rn(zv.z, __fadd_rn(q2, -zv.z));
        r.w = __fadd_rn(zv.w, __fadd_rn(q3, -zv.w));
        *reinterpret_cast<float4*>(out + off) = r;
    }
}

// ---------------------------------------------------------------------------
extern "C" void kernel_launch(void* const* d_in, const int* in_sizes, int n_in,
                              void* d_out, int out_size) {
    const float* z  = (const float*)d_in[0];
    const float* cb = (const float*)d_in[1];
    float* out = (float*)d_out;

    cudaFuncSetAttribute(mma_kernel,
                         cudaFuncAttributeMaxDynamicSharedMemorySize, MMA_SMEM);
    cudaFuncSetAttribute(rescore_kernel,
                         cudaFuncAttributeMaxDynamicSharedMemorySize, RS_SMEM);

    prep_kernel<<<PREP_GRID, 256>>>(z, cb);                            // 1
    mma_kernel<<<dim3(N_ROWS / 128, KCODES / 128), 256, MMA_SMEM>>>(); // 2
    rescore_kernel<<<NBUCK, 256, RS_SMEM>>>(z, cb);                    // 3
    gather_kernel<<<N_ROWS / GT, 256>>>(z, cb, out);                   // 4
}

// round 16
// speedup vs baseline: 1.1999x; 1.0779x over previous
#include <cuda_runtime.h>
#include <cuda_bf16.h>
#include <cuda_fp16.h>
#include <cstdint>

// Shapes (fixed): z (16,256,32,32) fp32; codebook (2048,256) fp32; out like z.
#define N_ROWS 16384
#define DDIM   256
#define KCODES 2048
#define HW     1024
#define NBUCK  256       // 64-token buckets
#define BCAP   8192      // per-bucket candidate cap

// fp16 coarse error budget: dot <= ||z||*||c||*2*2^-11 ~ 1.7e-4; + bf16 coarse
// store 4e-5 + reference grid rounding 6e-5 ~ 2.7e-4; enters twice -> 5.4e-4.
// MARGIN = 1.2e-3 keeps the 2.2x slack ratio validated across R7-R15.
#define MARGIN 1.2e-3f

// ---------------- device scratch (no mallocs allowed) ----------------
__device__ float              g_cnorm[KCODES];
__device__ uint32_t           g_minu[N_ROWS];
__device__ unsigned long long g_best[N_ROWS];
__device__ int                g_bcnt[NBUCK];
__device__ unsigned long long g_bcand[(size_t)NBUCK * BCAP]; // (coarse_bf16<<32)|(n<<11)|k
__device__ __half             g_zth[N_ROWS * DDIM];    // token-major fp16 z
__device__ __half             g_cbh[KCODES * DDIM];    // fp16 codebook

// ---------------- small helpers ----------------
__device__ __forceinline__ uint32_t fmap(float f) {
    uint32_t b = __float_as_uint(f);
    return (b & 0x80000000u) ? ~b : (b | 0x80000000u);
}
__device__ __forceinline__ float funmap(uint32_t u) {
    uint32_t b = (u & 0x80000000u) ? (u & 0x7fffffffu) : ~u;
    return __uint_as_float(b);
}
__device__ __forceinline__ void ldsm4(uint32_t& r0, uint32_t& r1, uint32_t& r2,
                                      uint32_t& r3, uint32_t addr) {
    asm volatile("ldmatrix.sync.aligned.m8n8.x4.shared.b16 {%0,%1,%2,%3}, [%4];"
                 : "=r"(r0), "=r"(r1), "=r"(r2), "=r"(r3) : "r"(addr));
}
__device__ __forceinline__ uint32_t smem_u32(const void* p) {
    uint32_t a;
    asm("{ .reg .u64 t; cvta.to.shared.u64 t, %1; cvt.u32.u64 %0, t; }" : "=r"(a) : "l"(p));
    return a;
}
__device__ __forceinline__ void mma16816(float* c, uint32_t a0, uint32_t a1,
                                         uint32_t a2, uint32_t a3,
                                         uint32_t b0, uint32_t b1) {
    asm volatile(
        "mma.sync.aligned.m16n8k16.row.col.f32.f16.f16.f32 "
        "{%0,%1,%2,%3}, {%4,%5,%6,%7}, {%8,%9}, {%0,%1,%2,%3};"
        : "+f"(c[0]), "+f"(c[1]), "+f"(c[2]), "+f"(c[3])
        : "r"(a0), "r"(a1), "r"(a2), "r"(a3), "r"(b0), "r"(b1));
}
__device__ __forceinline__ void cp16(uint32_t dst, const void* src) {
    asm volatile("cp.async.cg.shared.global [%0], [%1], 16;" :: "r"(dst), "l"(src));
}
__device__ __forceinline__ uint32_t pack_h2(float a, float b) {
    __half2 h = __floats2half2_rn(a, b);
    return *reinterpret_cast<uint32_t*>(&h);
}

// ---------------- (1) prep: transpose(fp16) + init + cbcnorm ---------------
#define PREP_T_CTAS 4096
#define PREP_I_CTAS 64
#define PREP_GRID   (PREP_T_CTAS + PREP_I_CTAS + 8)

__global__ void __launch_bounds__(256) prep_kernel(const float* __restrict__ z,
                                                   const float* __restrict__ cb) {
    const int bx = blockIdx.x, t = threadIdx.x;
    if (bx < PREP_T_CTAS) {
        __shared__ float ts[32][33];
        int tx = t & 31, ty = t >> 5;
        int b  = bx >> 8;
        int rest = bx & 255;
        int pt = rest & 31, dt = rest >> 5;
        int p0 = pt * 32, d0 = dt * 32;
        #pragma unroll
        for (int i = 0; i < 4; i++) {
            int d = d0 + ty + i * 8;
            ts[ty + i * 8][tx] = z[((size_t)(b * DDIM + d)) * HW + p0 + tx];
        }
        __syncthreads();
        #pragma unroll
        for (int i = 0; i < 4; i++) {
            int n = b * HW + p0 + ty + i * 8;
            g_zth[(size_t)n * DDIM + d0 + tx] = __float2half_rn(ts[tx][ty + i * 8]);
        }
    } else if (bx < PREP_T_CTAS + PREP_I_CTAS) {
        int n = (bx - PREP_T_CTAS) * 256 + t;
        g_minu[n] = 0xFFFFFFFFu;
        g_best[n] = 0xFFFFFFFFFFFFFFFFull;
        if (n < NBUCK) g_bcnt[n] = 0;
    } else {
        int k = (bx - PREP_T_CTAS - PREP_I_CTAS) * 256 + t;
        const float4* row4 = reinterpret_cast<const float4*>(cb + (size_t)k * DDIM);
        uint32_t* out = reinterpret_cast<uint32_t*>(g_cbh + (size_t)k * DDIM);
        float s = 0.f;
        #pragma unroll 4
        for (int d4 = 0; d4 < DDIM / 4; d4++) {
            float4 v = row4[d4];
            s = __fmaf_rn(v.x, v.x, s);   // sequential chain (matched JAX 13x)
            s = __fmaf_rn(v.y, v.y, s);
            s = __fmaf_rn(v.z, v.z, s);
            s = __fmaf_rn(v.w, v.w, s);
            out[d4 * 2 + 0] = pack_h2(v.x, v.y);
            out[d4 * 2 + 1] = pack_h2(v.z, v.w);
        }
        g_cnorm[k] = s;
    }
}

// ---------------- (2) coarse GEMM: R12 mainloop (fp16) + bucketed emission --
#define PITCH 72
#define A_BYTES (128 * PITCH * 2)        // 18432
#define STAGE_BYTES (2 * A_BYTES)        // 36864 (A + B per stage)
#define NSTAGE 3
#define MMA_SMEM (NSTAGE * STAGE_BYTES)  // 110592 dynamic

__global__ void __launch_bounds__(256, 2) mma_kernel() {
    extern __shared__ __align__(16) char dsm[];

    const int t = threadIdx.x, wid = t >> 5, lane = t & 31;
    const int row0 = blockIdx.x * 128, col0 = blockIdx.y * 128;
    const int wm = (wid & 3) * 32;
    const int wn = (wid >> 2) * 64;
    const int r  = lane >> 2, tt = lane & 3;
    const int grp = lane >> 3, l7 = lane & 7;

    const int a_row = (grp & 1) * 8 + l7, a_k = (grp & 2) * 4;
    const int b_row = (grp & 2) * 4 + l7, b_k = (grp & 1) * 8;
    const uint32_t sbase = smem_u32(dsm);
    uint32_t aOff[2], bOff[4];                   // stage-relative
    #pragma unroll
    for (int mt = 0; mt < 2; mt++)
        aOff[mt] = ((wm + mt * 16 + a_row) * PITCH + a_k) * 2;
    #pragma unroll
    for (int p = 0; p < 4; p++)
        bOff[p] = A_BYTES + ((wn + p * 16 + b_row) * PITCH + b_k) * 2;

    float acc[2][8][4];
    #pragma unroll
    for (int mt = 0; mt < 2; mt++)
        #pragma unroll
        for (int nt = 0; nt < 8; nt++)
            #pragma unroll
            for (int q = 0; q < 4; q++) acc[mt][nt][q] = 0.f;

    auto prefetch = [&](int ch) {
        const int s = ch % NSTAGE, cd0 = ch * 64;
        const uint32_t abuf = sbase + s * STAGE_BYTES;
        const uint32_t bbuf = abuf + A_BYTES;
        #pragma unroll
        for (int it = 0; it < 4; it++) {
            int idx = it * 256 + t;
            int rr = idx >> 3, k8 = (idx & 7) * 8;
            uint32_t off = (rr * PITCH + k8) * 2;
            cp16(abuf + off, &g_zth[(size_t)(row0 + rr) * DDIM + cd0 + k8]);
            cp16(bbuf + off, &g_cbh[(size_t)(col0 + rr) * DDIM + cd0 + k8]);
        }
        asm volatile("cp.async.commit_group;" ::: "memory");
    };

    prefetch(0);
    prefetch(1);
    for (int ch = 0; ch < 4; ch++) {
        if (ch < 3) asm volatile("cp.async.wait_group 1;" ::: "memory");
        else        asm volatile("cp.async.wait_group 0;" ::: "memory");
        __syncthreads();
        if (ch < 2) prefetch(ch + 2);

        const uint32_t sb = sbase + (ch % NSTAGE) * STAGE_BYTES;
        #pragma unroll
        for (int ks = 0; ks < 4; ks++) {
            const uint32_t koff = ks * 32;
            uint32_t A0[4], A1[4];
            ldsm4(A0[0], A0[1], A0[2], A0[3], sb + aOff[0] + koff);
            ldsm4(A1[0], A1[1], A1[2], A1[3], sb + aOff[1] + koff);
            #pragma unroll
            for (int p = 0; p < 4; p++) {
                uint32_t B[4];
                ldsm4(B[0], B[1], B[2], B[3], sb + bOff[p] + koff);
                mma16816(acc[0][2 * p],     A0[0], A0[1], A0[2], A0[3], B[0], B[1]);
                mma16816(acc[0][2 * p + 1], A0[0], A0[1], A0[2], A0[3], B[2], B[3]);
                mma16816(acc[1][2 * p],     A1[0], A1[1], A1[2], A1[3], B[0], B[1]);
                mma16816(acc[1][2 * p + 1], A1[0], A1[1], A1[2], A1[3], B[2], B[3]);
            }
        }
    }

    // --- epilogue: coarse = cnorm - 2*dot; warp row mins; bucketed emission --
    float rmin[2][2];
    #pragma unroll
    for (int mt = 0; mt < 2; mt++) { rmin[mt][0] = 3.4e38f; rmin[mt][1] = 3.4e38f; }
    #pragma unroll
    for (int mt = 0; mt < 2; mt++)
        #pragma unroll
        for (int nt = 0; nt < 8; nt++) {
            const int cbase = col0 + wn + nt * 8;
            float2 cn = *reinterpret_cast<const float2*>(&g_cnorm[cbase + tt * 2]);
            float d0 = __fmaf_rn(-2.f, acc[mt][nt][0], cn.x);
            float d1 = __fmaf_rn(-2.f, acc[mt][nt][1], cn.y);
            float d2 = __fmaf_rn(-2.f, acc[mt][nt][2], cn.x);
            float d3 = __fmaf_rn(-2.f, acc[mt][nt][3], cn.y);
            acc[mt][nt][0] = d0; acc[mt][nt][1] = d1;
            acc[mt][nt][2] = d2; acc[mt][nt][3] = d3;
            rmin[mt][0] = fminf(rmin[mt][0], fminf(d0, d1));
            rmin[mt][1] = fminf(rmin[mt][1], fminf(d2, d3));
        }
    #pragma unroll
    for (int mt = 0; mt < 2; mt++)
        #pragma unroll
        for (int h = 0; h < 2; h++)
            #pragma unroll
            for (int off = 1; off < 4; off <<= 1)
                rmin[mt][h] = fminf(rmin[mt][h],
                                    __shfl_xor_sync(0xffffffffu, rmin[mt][h], off));

    float gmv[2][2];
    if (tt == 0) {
        #pragma unroll
        for (int mt = 0; mt < 2; mt++) {
            const int grow = row0 + wm + mt * 16 + r;
            uint32_t o0 = atomicMin(&g_minu[grow],     fmap(rmin[mt][0]));
            uint32_t o1 = atomicMin(&g_minu[grow + 8], fmap(rmin[mt][1]));
            gmv[mt][0] = funmap(o0);   // NaN if untouched; fminf ignores NaN
            gmv[mt][1] = funmap(o1);
        }
    }
    const int src = lane & ~3;
    float th[2][2];
    #pragma unroll
    for (int mt = 0; mt < 2; mt++)
        #pragma unroll
        for (int h = 0; h < 2; h++) {
            float g = __shfl_sync(0xffffffffu, gmv[mt][h], src);
            th[mt][h] = fminf(rmin[mt][h], g) + (MARGIN + 1e-4f);
        }

    // all of this warp's rows (wm..wm+31) lie in ONE 64-token bucket
    const int bkt = (row0 >> 6) + (wm >= 64 ? 1 : 0);

    int cnt = 0;
    #pragma unroll
    for (int mt = 0; mt < 2; mt++)
        #pragma unroll
        for (int nt = 0; nt < 8; nt++)
            #pragma unroll
            for (int q = 0; q < 4; q++)
                cnt += (acc[mt][nt][q] <= th[mt][q >> 1]) ? 1 : 0;

    int pref = cnt;
    #pragma unroll
    for (int off = 1; off < 32; off <<= 1) {
        int v = __shfl_up_sync(0xffffffffu, pref, off);
        if (lane >= off) pref += v;
    }
    int excl = pref - cnt;
    int wbase = 0;
    if (lane == 31 && pref > 0) wbase = atomicAdd(&g_bcnt[bkt], pref);
    wbase = __shfl_sync(0xffffffffu, wbase, 31);
    int pos = wbase + excl;

    unsigned long long* bdst = g_bcand + (size_t)bkt * BCAP;
    #pragma unroll
    for (int mt = 0; mt < 2; mt++)
        #pragma unroll
        for (int nt = 0; nt < 8; nt++)
            #pragma unroll
            for (int q = 0; q < 4; q++) {
                float d = acc[mt][nt][q];
                if (d <= th[mt][q >> 1]) {
                    if (pos < BCAP) {
                        int grow = row0 + wm + mt * 16 + r + ((q >> 1) ? 8 : 0);
                        int k    = col0 + wn + nt * 8 + tt * 2 + (q & 1);
                        uint32_t dbits =
                            (uint32_t)__bfloat16_as_ushort(__float2bfloat16(d));
                        bdst[pos] = ((unsigned long long)dbits << 32)
                                  | ((uint32_t)grow << 11) | (uint32_t)k;
                    }
                    pos++;
                }
            }
}

// ---------------- (3) rescore: bucket CTA stages its z tile from z ----------
#define RPITCH 261
#define RS_SMEM (64 * RPITCH * 4)   // 66816 bytes

__global__ void __launch_bounds__(256) rescore_kernel(const float* __restrict__ z,
                                                      const float* __restrict__ cb) {
    extern __shared__ float zt[];   // [64 tokens][RPITCH]
    const int bkt = blockIdx.x, t = threadIdx.x;
    const int n0 = bkt * 64;
    const int b = n0 >> 10, p0 = n0 & 1023;   // 64 | 1024 -> single b

    #pragma unroll
    for (int it = 0; it < 16; it++) {
        int idx = it * 256 + t;
        int d = idx >> 4, s = idx & 15;
        float4 v = *reinterpret_cast<const float4*>(
            &z[((size_t)(b * DDIM + d)) * HW + p0 + s * 4]);
        zt[(s * 4 + 0) * RPITCH + d] = v.x;
        zt[(s * 4 + 1) * RPITCH + d] = v.y;
        zt[(s * 4 + 2) * RPITCH + d] = v.z;
        zt[(s * 4 + 3) * RPITCH + d] = v.w;
    }
    __syncthreads();

    int cnt = g_bcnt[bkt]; if (cnt > BCAP) cnt = BCAP;
    const unsigned long long* bc = g_bcand + (size_t)bkt * BCAP;
    for (int i = t; i < cnt; i += 256) {
        unsigned long long e = bc[i];
        uint32_t nk = (uint32_t)e & 0x1FFFFFFu;
        int n = nk >> 11, k = nk & 2047;
        float coarse =
            __bfloat162float(__ushort_as_bfloat16((unsigned short)(e >> 32)));
        if (coarse <= funmap(g_minu[n]) + MARGIN) {
            const float* zr = zt + (n & 63) * RPITCH;
            const float4* ca4 = reinterpret_cast<const float4*>(cb + (size_t)k * DDIM);
            float acc = 0.f, zn = 0.f;
            #pragma unroll 8
            for (int d4 = 0; d4 < DDIM / 4; d4++) {
                float a0 = zr[d4 * 4 + 0], a1 = zr[d4 * 4 + 1];
                float a2 = zr[d4 * 4 + 2], a3 = zr[d4 * 4 + 3];
                float4 c = ca4[d4];
                zn  = __fmaf_rn(a0, a0, zn);     // znorm chain (verified 13x)
                zn  = __fmaf_rn(a1, a1, zn);
                zn  = __fmaf_rn(a2, a2, zn);
                zn  = __fmaf_rn(a3, a3, zn);
                acc = __fmaf_rn(a0, c.x, acc);   // dot chain (verified 13x)
                acc = __fmaf_rn(a1, c.y, acc);
                acc = __fmaf_rn(a2, c.z, acc);
                acc = __fmaf_rn(a3, c.w, acc);
            }
            float dist = __fadd_rn(__fadd_rn(zn, g_cnorm[k]), -2.0f * acc);
            unsigned long long pk =
                ((unsigned long long)__float_as_uint(dist) << 32) | (unsigned)k;
            atomicMin(&g_best[n], pk);
        }
    }
}

// ---------------- (4) gather + STE with smem-staged codebook rows ----------
#define GT 32   // tokens per CTA

__global__ void __launch_bounds__(256) gather_kernel(const float* __restrict__ z,
                                                     const float* __restrict__ cb,
                                                     float* __restrict__ out) {
    __shared__ float cbrow[GT][DDIM + 1];
    __shared__ int ks[GT];
    const int t = threadIdx.x;
    const int n0 = blockIdx.x * GT;
    const int b = n0 >> 10, p0 = n0 & 1023;

    if (t < GT) ks[t] = (int)(g_best[n0 + t] & 0xffffffffu);
    __syncthreads();

    #pragma unroll
    for (int it = 0; it < (GT * DDIM / 4) / 256; it++) {
        int slot = it * 256 + t;
        int tok = slot >> 6, c4 = slot & 63;
        float4 v = reinterpret_cast<const float4*>(cb + (size_t)ks[tok] * DDIM)[c4];
        cbrow[tok][c4 * 4 + 0] = v.x;
        cbrow[tok][c4 * 4 + 1] = v.y;
        cbrow[tok][c4 * 4 + 2] = v.z;
        cbrow[tok][c4 * 4 + 3] = v.w;
    }
    __syncthreads();

    const size_t zbase = (size_t)b * DDIM * HW + p0;
    #pragma unroll
    for (int it = 0; it < 8; it++) {
        int slot = it * 256 + t;
        int d = slot >> 3, p4 = slot & 7;
        size_t off = zbase + (size_t)d * HW + p4 * 4;
        float4 zv = *reinterpret_cast<const float4*>(z + off);
        float q0 = cbrow[p4 * 4 + 0][d];
        float q1 = cbrow[p4 * 4 + 1][d];
        float q2 = cbrow[p4 * 4 + 2][d];
        float q3 = cbrow[p4 * 4 + 3][d];
        float4 r;
        r.x = __fadd_rn(zv.x, __fadd_rn(q0, -zv.x));   // STE chain (matched 13x)
        r.y = __fadd_rn(zv.y, __fadd_rn(q1, -zv.y));
        r.z = __fadd_rn(zv.z, __fadd_rn(q2, -zv.z));
        r.w = __fadd_rn(zv.w, __fadd_rn(q3, -zv.w));
        *reinterpret_cast<float4*>(out + off) = r;
    }
}

// ---------------------------------------------------------------------------
extern "C" void kernel_launch(void* const* d_in, const int* in_sizes, int n_in,
                              void* d_out, int out_size) {
    const float* z  = (const float*)d_in[0];
    const float* cb = (const float*)d_in[1];
    float* out = (float*)d_out;

    cudaFuncSetAttribute(mma_kernel,
                         cudaFuncAttributeMaxDynamicSharedMemorySize, MMA_SMEM);
    cudaFuncSetAttribute(rescore_kernel,
                         cudaFuncAttributeMaxDynamicSharedMemorySize, RS_SMEM);

    prep_kernel<<<PREP_GRID, 256>>>(z, cb);                            // 1
    mma_kernel<<<dim3(N_ROWS / 128, KCODES / 128), 256, MMA_SMEM>>>(); // 2
    rescore_kernel<<<NBUCK, 256, RS_SMEM>>>(z, cb);                    // 3
    gather_kernel<<<N_ROWS / GT, 256>>>(z, cb, out);                   // 4
}